// round 1
// baseline (speedup 1.0000x reference)
#include <cuda_runtime.h>
#include <math.h>

#define LC      2048          // coarse length L / 8
#define CCH     64            // channels
#define IOROWS  4096          // 64*64 weight elements per k
#define CINV    0.35355339059327373f   // 1/(2*sqrt(2))

// Transposed weights: [which(2)][k(2048)][i*64+o]  => 64 MB scratch
__device__ float g_wt[2][(size_t)LC * IOROWS];

// ---------------------------------------------------------------------------
// Kernel 1: transpose w_approx / w_detail from (i,o,l) -> (l, i*64+o)
// src viewed as [IOROWS=4096 rows][LC=2048 cols]; dst = [LC][IOROWS]
// ---------------------------------------------------------------------------
__global__ void transpose_w_kernel(const float* __restrict__ wA,
                                   const float* __restrict__ wD) {
    __shared__ float tile[32][33];
    const float* src = (blockIdx.z == 0) ? wA : wD;
    float* dst = g_wt[blockIdx.z];
    int lbase  = blockIdx.x * 32;
    int iobase = blockIdx.y * 32;
    int tx = threadIdx.x, ty = threadIdx.y;   // block (32, 8)
#pragma unroll
    for (int r = 0; r < 32; r += 8)
        tile[ty + r][tx] = src[(size_t)(iobase + ty + r) * LC + (lbase + tx)];
    __syncthreads();
#pragma unroll
    for (int r = 0; r < 32; r += 8)
        dst[(size_t)(lbase + ty + r) * IOROWS + (iobase + tx)] = tile[tx][ty + r];
}

__device__ __forceinline__ float gelu_tanh(float v) {
    float inner = 0.7978845608028654f * (v + 0.044715f * v * v * v);
    return 0.5f * v * (1.0f + tanhf(inner));
}

// ---------------------------------------------------------------------------
// Kernel 2: fused wavelet block.
// grid = (2048 k-positions, 4 batch-groups), block = 256 threads.
// Per batch (8 per block):
//   warps 0-3 : u/v reduction + two 64x64 matvecs (a3', d3') from smem weights
//   warps 4-7 : skip matmul (8 rows x 64 cols), 4-wide float4 tiles, W_skip via L1
//   warps 4-7 : combine + gelu + float4 store
// ---------------------------------------------------------------------------
__global__ __launch_bounds__(256) void wavelet_main_kernel(
    const float* __restrict__ x, const float* __restrict__ Ws,
    const float* __restrict__ bsk_g, float* __restrict__ out)
{
    __shared__ float wa[IOROWS];        // 16 KB  w_approx[:, :, k]  as [i*64+o]
    __shared__ float wd[IOROWS];        // 16 KB  w_detail[:, :, k]
    __shared__ float xs[8 * 64];        // 2 KB   current 8-sample block
    __shared__ float uv[2][64];         // u, v
    __shared__ float ad[2][64];         // c*(a3'-u), c*(d3'-v)
    __shared__ float bsk[64];

    const int k   = blockIdx.x;
    const int tid = threadIdx.x;
    const float* wtA = g_wt[0] + (size_t)k * IOROWS;
    const float* wtD = g_wt[1] + (size_t)k * IOROWS;

    for (int i = tid; i < IOROWS; i += 256) {
        wa[i] = wtA[i];
        wd[i] = wtD[i];
    }
    if (tid < 64) bsk[tid] = bsk_g[tid];
    __syncthreads();

    const int o  = tid & 63;
    const int t  = tid - 128;           // valid for skip threads
    const int og = (t & 15) * 4;        // 4-wide output-channel group
    const int j  = t >> 4;              // row 0..7 within the 8-block

    const int bstart = blockIdx.y * 8;
    for (int b = bstart; b < bstart + 8; ++b) {
        const float* xp = x   + ((size_t)b * 16384 + (size_t)k * 8) * 64;
        float*       op = out + ((size_t)b * 16384 + (size_t)k * 8) * 64;

        xs[tid]       = xp[tid];
        xs[tid + 256] = xp[tid + 256];
        __syncthreads();

        // ---- u/v (warps 0-3; cheap) ----
        if (tid < 128) {
            float e = 0.f, l2 = 0.f;
#pragma unroll
            for (int jj = 0; jj < 4; jj++) {
                e  += xs[jj * 64 + o];
                l2 += xs[(jj + 4) * 64 + o];
            }
            uv[tid >> 6][o] = (tid < 64) ? CINV * (e + l2) : CINV * (e - l2);
        }
        __syncthreads();

        float acc0 = 0.f, acc1 = 0.f, acc2 = 0.f, acc3 = 0.f;
        if (tid < 128) {
            // ---- matvecs: a3'[o] / d3'[o] ----
            const float* W = (tid < 64) ? wa : wd;
            const float* u = uv[tid >> 6];
            float a = 0.f;
#pragma unroll 8
            for (int i = 0; i < 64; i++) a = fmaf(u[i], W[i * 64 + o], a);
            ad[tid >> 6][o] = CINV * (a - u[o]);
        } else {
            // ---- skip matmul: 1 row j, 4 output channels og..og+3 ----
            const float4* Wsv = reinterpret_cast<const float4*>(Ws);
#pragma unroll 8
            for (int c = 0; c < 64; c++) {
                float4 w4 = __ldg(&Wsv[c * 16 + (og >> 2)]);
                float  xv = xs[j * 64 + c];
                acc0 = fmaf(xv, w4.x, acc0);
                acc1 = fmaf(xv, w4.y, acc1);
                acc2 = fmaf(xv, w4.z, acc2);
                acc3 = fmaf(xv, w4.w, acc3);
            }
        }
        __syncthreads();

        // ---- combine + gelu + store (warps 4-7 own the 512 outputs) ----
        if (tid >= 128) {
            float sgn = (j < 4) ? 1.f : -1.f;
            float4 r;
            {
                float v0 = xs[j*64+og+0] + ad[0][og+0] + sgn*ad[1][og+0] + acc0 + bsk[og+0];
                float v1 = xs[j*64+og+1] + ad[0][og+1] + sgn*ad[1][og+1] + acc1 + bsk[og+1];
                float v2 = xs[j*64+og+2] + ad[0][og+2] + sgn*ad[1][og+2] + acc2 + bsk[og+2];
                float v3 = xs[j*64+og+3] + ad[0][og+3] + sgn*ad[1][og+3] + acc3 + bsk[og+3];
                r.x = gelu_tanh(v0);
                r.y = gelu_tanh(v1);
                r.z = gelu_tanh(v2);
                r.w = gelu_tanh(v3);
            }
            *reinterpret_cast<float4*>(op + j * 64 + og) = r;
        }
        __syncthreads();   // xs reused next batch
    }
}

extern "C" void kernel_launch(void* const* d_in, const int* in_sizes, int n_in,
                              void* d_out, int out_size) {
    const float* x  = (const float*)d_in[0];   // (32, 16384, 64)
    const float* wA = (const float*)d_in[1];   // (64, 64, 2048)
    const float* wD = (const float*)d_in[2];   // (64, 64, 2048)
    const float* Ws = (const float*)d_in[3];   // (64, 64)
    const float* bs = (const float*)d_in[4];   // (64,)
    float* out = (float*)d_out;

    dim3 tb(32, 8), tg(LC / 32, IOROWS / 32, 2);
    transpose_w_kernel<<<tg, tb>>>(wA, wD);

    dim3 mg(LC, 4);
    wavelet_main_kernel<<<mg, 256>>>(x, Ws, bs, out);
}

// round 2
// speedup vs baseline: 2.2594x; 2.2594x over previous
#include <cuda_runtime.h>
#include <math.h>

#define LC   2048
#define CINV 0.35355339059327373f   // 1/(2*sqrt(2))

// Scratch: transposed weights [which][k][i*64+o], UV [k][which][b][i], AD [k][which][b][o]
__device__ float g_wt[2][(size_t)LC * 4096];
__device__ float g_uv[(size_t)LC * 4096];
__device__ float g_ad[(size_t)LC * 4096];

// ---------------------------------------------------------------------------
// Kernel 1: transpose w_approx / w_detail from (i,o,l) -> (l, i*64+o)
// ---------------------------------------------------------------------------
__global__ void transpose_w_kernel(const float* __restrict__ wA,
                                   const float* __restrict__ wD) {
    __shared__ float tile[32][33];
    const float* src = (blockIdx.z == 0) ? wA : wD;
    float* dst = g_wt[blockIdx.z];
    int lbase  = blockIdx.x * 32;
    int iobase = blockIdx.y * 32;
    int tx = threadIdx.x, ty = threadIdx.y;   // block (32, 8)
#pragma unroll
    for (int r = 0; r < 32; r += 8)
        tile[ty + r][tx] = src[(size_t)(iobase + ty + r) * LC + (lbase + tx)];
    __syncthreads();
#pragma unroll
    for (int r = 0; r < 32; r += 8)
        dst[(size_t)(lbase + ty + r) * 4096 + (iobase + tx)] = tile[tx][ty + r];
}

// ---------------------------------------------------------------------------
// Kernel 2: u/v per (b, k, o).  u = c*sum(x[8k..8k+8]), v = c*(first4 - last4)
// ---------------------------------------------------------------------------
__global__ __launch_bounds__(256) void uv_kernel(const float* __restrict__ x) {
    int t = blockIdx.x * 256 + threadIdx.x;
    int o = t & 63;
    int k = (t >> 6) & (LC - 1);
    int b = t >> 17;
    const float* xp = x + ((size_t)b * 16384 + (size_t)k * 8) * 64 + o;
    float e = 0.f, d = 0.f;
#pragma unroll
    for (int j = 0; j < 4; j++) { e += xp[j * 64]; d += xp[(j + 4) * 64]; }
    size_t base = (size_t)k * 4096 + (size_t)b * 64 + o;  // [k][0][b][o]
    g_uv[base]        = CINV * (e + d);
    g_uv[base + 2048] = CINV * (e - d);
}

// ---------------------------------------------------------------------------
// Kernel 3: corrections A/D[k][which][b][o] = c*(dot(uv, W col o) - uv[o])
// One block per k. 256 threads, each owns (which, 4 batches, 4 outputs).
// ---------------------------------------------------------------------------
__global__ __launch_bounds__(256) void stagea_kernel() {
    extern __shared__ float sm[];
    float* wsm = sm;           // [2][4096]
    float* us  = sm + 8192;    // [2][i*33 + b], 2*2112

    int k = blockIdx.x, tid = threadIdx.x;
    for (int i = tid; i < 4096; i += 256) {
        wsm[i]        = g_wt[0][(size_t)k * 4096 + i];
        wsm[4096 + i] = g_wt[1][(size_t)k * 4096 + i];
    }
    const float* uvg = g_uv + (size_t)k * 4096;
    for (int p = tid; p < 4096; p += 256) {
        int which = p >> 11, b = (p >> 6) & 31, i = p & 63;
        us[which * 2112 + i * 33 + b] = uvg[p];
    }
    __syncthreads();

    int which = tid >> 7;
    int r  = tid & 127;
    int b0 = (r >> 4) * 4;
    int og = (r & 15) * 4;
    const float* W = wsm + which * 4096;
    const float* U = us + which * 2112;

    float acc[4][4] = {};
#pragma unroll 8
    for (int i = 0; i < 64; i++) {
        float4 w4 = *(const float4*)(W + i * 64 + og);
#pragma unroll
        for (int bb = 0; bb < 4; bb++) {
            float uu = U[i * 33 + b0 + bb];
            acc[bb][0] = fmaf(uu, w4.x, acc[bb][0]);
            acc[bb][1] = fmaf(uu, w4.y, acc[bb][1]);
            acc[bb][2] = fmaf(uu, w4.z, acc[bb][2]);
            acc[bb][3] = fmaf(uu, w4.w, acc[bb][3]);
        }
    }
    float* adg = g_ad + (size_t)k * 4096 + which * 2048;
#pragma unroll
    for (int bb = 0; bb < 4; bb++)
#pragma unroll
        for (int c = 0; c < 4; c++)
            adg[(b0 + bb) * 64 + og + c] =
                CINV * (acc[bb][c] - U[(og + c) * 33 + b0 + bb]);
}

__device__ __forceinline__ float gelu_tanh(float v) {
    float inner = 0.7978845608028654f * (v + 0.044715f * v * v * v);
    return 0.5f * v * (1.0f + tanhf(inner));
}

// ---------------------------------------------------------------------------
// Kernel 4: main GEMM + epilogue.
// out[b, 8k+j, o] = gelu( x_row . (W_skip + I)[:,o] + A[o] + sgn_j*D[o] + bias[o] )
// One block per k, 512 threads. Thread micro-tile: 8 rows (one batch's 8
// samples) x 4 output cols. 1.5 B smem per FMA.
// ---------------------------------------------------------------------------
__global__ __launch_bounds__(512) void wavelet_main_kernel(
    const float* __restrict__ x, const float* __restrict__ Ws,
    const float* __restrict__ bsk, float* __restrict__ out)
{
    extern __shared__ float sm[];
    float* xs   = sm;            // 32 batches * (512 + 8 pad) = 16640
    float* wsk  = sm + 16640;    // 4096  (W_skip + I)
    float* ads  = wsk + 4096;    // 4096  [which][b][o]
    float* bias = ads + 4096;    // 64

    const int k = blockIdx.x, tid = threadIdx.x;

    for (int i = tid; i < 4096; i += 512) {
        float v = Ws[i];
        if ((i >> 6) == (i & 63)) v += 1.0f;
        wsk[i] = v;
    }
    const float* adg = g_ad + (size_t)k * 4096;
    for (int i = tid; i < 4096; i += 512) ads[i] = adg[i];
    if (tid < 64) bias[tid] = bsk[tid];

    const float4* x4  = (const float4*)x;
    float4*       xs4 = (float4*)xs;
#pragma unroll
    for (int it = 0; it < 8; it++) {
        int idx = tid + it * 512;           // 0..4095 float4s
        int b = idx >> 7, r = idx & 127;
        xs4[b * 130 + r] = x4[(size_t)b * 262144 + (size_t)k * 128 + r];
    }
    __syncthreads();

    const int b  = tid >> 4;
    const int cg = (tid & 15) << 2;
    const float* xb = xs + b * 520;

    float acc[8][4] = {};
#pragma unroll 8
    for (int kk = 0; kk < 64; kk += 2) {
        float4 w0 = *(const float4*)(wsk + kk * 64 + cg);
        float4 w1 = *(const float4*)(wsk + (kk + 1) * 64 + cg);
        float2 xv[8];
#pragma unroll
        for (int j = 0; j < 8; j++)
            xv[j] = *(const float2*)(xb + j * 64 + kk);
#pragma unroll
        for (int j = 0; j < 8; j++) {
            acc[j][0] = fmaf(xv[j].x, w0.x, acc[j][0]);
            acc[j][0] = fmaf(xv[j].y, w1.x, acc[j][0]);
            acc[j][1] = fmaf(xv[j].x, w0.y, acc[j][1]);
            acc[j][1] = fmaf(xv[j].y, w1.y, acc[j][1]);
            acc[j][2] = fmaf(xv[j].x, w0.z, acc[j][2]);
            acc[j][2] = fmaf(xv[j].y, w1.z, acc[j][2]);
            acc[j][3] = fmaf(xv[j].x, w0.w, acc[j][3]);
            acc[j][3] = fmaf(xv[j].y, w1.w, acc[j][3]);
        }
    }

    float4 A  = *(const float4*)(ads + b * 64 + cg);
    float4 Dv = *(const float4*)(ads + 2048 + b * 64 + cg);
    float4 Bb = *(const float4*)(bias + cg);
    float* op = out + ((size_t)b * 16384 + (size_t)k * 8) * 64 + cg;
#pragma unroll
    for (int j = 0; j < 8; j++) {
        float sgn = (j < 4) ? 1.f : -1.f;
        float4 rv;
        rv.x = gelu_tanh(acc[j][0] + A.x + sgn * Dv.x + Bb.x);
        rv.y = gelu_tanh(acc[j][1] + A.y + sgn * Dv.y + Bb.y);
        rv.z = gelu_tanh(acc[j][2] + A.z + sgn * Dv.z + Bb.z);
        rv.w = gelu_tanh(acc[j][3] + A.w + sgn * Dv.w + Bb.w);
        *(float4*)(op + j * 64) = rv;
    }
}

extern "C" void kernel_launch(void* const* d_in, const int* in_sizes, int n_in,
                              void* d_out, int out_size) {
    const float* x  = (const float*)d_in[0];   // (32, 16384, 64)
    const float* wA = (const float*)d_in[1];   // (64, 64, 2048)
    const float* wD = (const float*)d_in[2];   // (64, 64, 2048)
    const float* Ws = (const float*)d_in[3];   // (64, 64)
    const float* bs = (const float*)d_in[4];   // (64,)
    float* out = (float*)d_out;

    static bool attrs_set = false;
    // idempotent + cheap; safe to call every launch (not a graph node)
    cudaFuncSetAttribute(stagea_kernel,
        cudaFuncAttributeMaxDynamicSharedMemorySize, 49664);
    cudaFuncSetAttribute(wavelet_main_kernel,
        cudaFuncAttributeMaxDynamicSharedMemorySize, 99584);
    (void)attrs_set;

    dim3 tb(32, 8), tg(LC / 32, 4096 / 32, 2);
    transpose_w_kernel<<<tg, tb>>>(wA, wD);

    uv_kernel<<<(32 * LC * 64) / 256, 256>>>(x);

    stagea_kernel<<<LC, 256, 49664>>>();

    wavelet_main_kernel<<<LC, 512, 99584>>>(x, Ws, bs, out);
}